// round 2
// baseline (speedup 1.0000x reference)
#include <cuda_runtime.h>

#define DM   2048     // d_model
#define DL   512      // d_latent
#define NH   16
#define HD   128
#define SEQ  2048
#define NB   2
#define TOK  (NB*SEQ) // 4096

// Scratch (allocation-free rule: __device__ globals, referenced ONLY in device code)
__device__ float g_q  [TOK*DM];
__device__ float g_ckv[TOK*DL];
__device__ float g_k  [TOK*DM];
__device__ float g_v  [TOK*DM];
__device__ float g_ctx[TOK*DM];

// ---------------------------------------------------------------------------
// C[M,N] = A[M,K] @ B[N,K]^T  (+ optional bias[N])
// 128x128 tile, BK=16, 256 threads, 8x8 per-thread register blocking.
// MODE binds scratch buffers in device code (no cudaGetSymbolAddress on host):
//   0: C=g_ckv, A=arg      (c_kv = x @ W_dkv^T)
//   1: C=g_q,   A=arg      (q    = x @ W_q^T)
//   2: C=g_k,   A=g_ckv    (k    = c_kv @ W_uk^T)
//   3: C=g_v,   A=g_ckv    (v    = c_kv @ W_uv^T)
//   4: C=arg,   A=g_ctx    (out  = ctx @ W_o^T + b)
// ---------------------------------------------------------------------------
template<int MODE>
__global__ __launch_bounds__(256) void sgemm_nt(
    const float* __restrict__ Aarg, const float* __restrict__ B,
    const float* __restrict__ bias, float* __restrict__ Carg,
    int M, int N, int K)
{
    const float* A;
    float* C;
    if      (MODE == 0) { A = Aarg;  C = g_ckv; }
    else if (MODE == 1) { A = Aarg;  C = g_q;   }
    else if (MODE == 2) { A = g_ckv; C = g_k;   }
    else if (MODE == 3) { A = g_ckv; C = g_v;   }
    else                { A = g_ctx; C = Carg;  }

    const int BK = 16;
    __shared__ float As[BK][128];
    __shared__ float Bs[BK][128];

    int tid  = threadIdx.x;
    int tx   = tid & 15;      // 0..15 -> 8 cols each
    int ty   = tid >> 4;      // 0..15 -> 8 rows each
    int row0 = blockIdx.y * 128;
    int col0 = blockIdx.x * 128;

    float acc[8][8];
#pragma unroll
    for (int i = 0; i < 8; i++)
#pragma unroll
        for (int j = 0; j < 8; j++) acc[i][j] = 0.f;

    int lr = tid >> 2;   // 0..63 : tile row for loads
    int lc = tid & 3;    // 0..3  : float4 within the 16-wide k slice

    for (int k0 = 0; k0 < K; k0 += BK) {
#pragma unroll
        for (int l = 0; l < 2; l++) {
            int r = lr + l * 64;
            float4 va = *(const float4*)(A + (size_t)(row0 + r) * K + k0 + lc * 4);
            As[lc*4+0][r] = va.x; As[lc*4+1][r] = va.y;
            As[lc*4+2][r] = va.z; As[lc*4+3][r] = va.w;
            float4 vb = *(const float4*)(B + (size_t)(col0 + r) * K + k0 + lc * 4);
            Bs[lc*4+0][r] = vb.x; Bs[lc*4+1][r] = vb.y;
            Bs[lc*4+2][r] = vb.z; Bs[lc*4+3][r] = vb.w;
        }
        __syncthreads();

#pragma unroll
        for (int kk = 0; kk < BK; kk++) {
            float a[8], b[8];
#pragma unroll
            for (int i = 0; i < 8; i++) a[i] = As[kk][ty * 8 + i];
#pragma unroll
            for (int j = 0; j < 8; j++) b[j] = Bs[kk][tx * 8 + j];
#pragma unroll
            for (int i = 0; i < 8; i++)
#pragma unroll
                for (int j = 0; j < 8; j++)
                    acc[i][j] += a[i] * b[j];
        }
        __syncthreads();
    }

#pragma unroll
    for (int i = 0; i < 8; i++) {
        int row = row0 + ty * 8 + i;
#pragma unroll
        for (int j = 0; j < 8; j++) {
            int col = col0 + tx * 8 + j;
            float v = acc[i][j];
            if (MODE == 4) v += bias[col];
            C[(size_t)row * N + col] = v;
        }
    }
}

// ---------------------------------------------------------------------------
// Causal flash attention, fp32, reads g_q/g_k/g_v, writes g_ctx.
// grid = (SEQ/32, NB*NH), block = 128 threads.
// Thread layout: tq = tid/4 (query in tile), td = tid%4 (32-dim slice of HD).
// Q/K/V layout: [token, DM] with head slice at column h*HD (gemm output as-is).
// ---------------------------------------------------------------------------
__global__ __launch_bounds__(128) void attn_kernel()
{
    const int BQ = 32, BKT = 32;
    __shared__ float Ks[BKT][HD];
    __shared__ float Vs[BKT][HD];

    int tid = threadIdx.x;
    int tq  = tid >> 2;        // 0..31
    int td  = tid & 3;         // 0..3
    int dbase = td * 32;

    int bh = blockIdx.y;
    int b  = bh >> 4;
    int h  = bh & 15;
    int q0 = blockIdx.x * BQ;
    int qrow = b * SEQ + q0 + tq;

    const float scale = 0.08838834764831845f;  // 1/sqrt(128)
    const float* qp = g_q + (size_t)qrow * DM + h * HD + dbase;
    float qreg[32];
#pragma unroll
    for (int d = 0; d < 32; d++) qreg[d] = qp[d] * scale;

    float acc[32];
#pragma unroll
    for (int d = 0; d < 32; d++) acc[d] = 0.f;
    float m = -1e30f, l = 0.f;

    int nkt = q0 / BKT + 1;  // causal: only k-tiles with k0 <= q0
    for (int kt = 0; kt < nkt; kt++) {
        int k0 = kt * BKT;
        __syncthreads();
#pragma unroll
        for (int i = 0; i < 8; i++) {
            int idx = tid + i * 128;           // 0..1023
            int r = idx >> 5;                  // 0..31
            int c = (idx & 31) * 4;            // 0..124
            size_t base = (size_t)(b * SEQ + k0 + r) * DM + h * HD + c;
            *(float4*)&Ks[r][c] = *(const float4*)(g_k + base);
            *(float4*)&Vs[r][c] = *(const float4*)(g_v + base);
        }
        __syncthreads();

        float s[32];
#pragma unroll
        for (int kk = 0; kk < 32; kk++) {
            float p = 0.f;
#pragma unroll
            for (int d = 0; d < 32; d++) p += qreg[d] * Ks[kk][dbase + d];
            p += __shfl_xor_sync(0xffffffffu, p, 1);
            p += __shfl_xor_sync(0xffffffffu, p, 2);
            s[kk] = (k0 + kk <= q0 + tq) ? p : -1e30f;
        }

        float mt = m;
#pragma unroll
        for (int kk = 0; kk < 32; kk++) mt = fmaxf(mt, s[kk]);

        float corr = __expf(m - mt);
        l *= corr;
#pragma unroll
        for (int d = 0; d < 32; d++) acc[d] *= corr;

#pragma unroll
        for (int kk = 0; kk < 32; kk++) {
            float pk = __expf(s[kk] - mt);
            l += pk;
#pragma unroll
            for (int d = 0; d < 32; d++) acc[d] += pk * Vs[kk][dbase + d];
        }
        m = mt;
    }

    float inv = 1.f / l;
    float* op = g_ctx + (size_t)qrow * DM + h * HD + dbase;
#pragma unroll
    for (int d = 0; d < 32; d++) op[d] = acc[d] * inv;
}

// ---------------------------------------------------------------------------
// Launch: projections -> flash attention -> output projection (+bias)
// Pure kernel launches; no other CUDA API calls (graph-capture safe).
// ---------------------------------------------------------------------------
extern "C" void kernel_launch(void* const* d_in, const int* in_sizes, int n_in,
                              void* d_out, int out_size)
{
    (void)in_sizes; (void)n_in; (void)out_size;
    const float* x    = (const float*)d_in[0];
    const float* W_q  = (const float*)d_in[1];
    const float* W_dkv= (const float*)d_in[2];
    const float* W_uk = (const float*)d_in[3];
    const float* W_uv = (const float*)d_in[4];
    const float* W_o  = (const float*)d_in[5];
    const float* W_b  = (const float*)d_in[6];
    float* out = (float*)d_out;

    dim3 blk(256);
    // c_kv = x @ W_dkv^T            [4096, 512]
    sgemm_nt<0><<<dim3(DL/128, TOK/128), blk>>>(x, W_dkv, nullptr, nullptr, TOK, DL, DM);
    // q = x @ W_q^T                 [4096, 2048]
    sgemm_nt<1><<<dim3(DM/128, TOK/128), blk>>>(x, W_q, nullptr, nullptr, TOK, DM, DM);
    // k = c_kv @ W_uk^T             [4096, 2048]
    sgemm_nt<2><<<dim3(DM/128, TOK/128), blk>>>(nullptr, W_uk, nullptr, nullptr, TOK, DM, DL);
    // v = c_kv @ W_uv^T             [4096, 2048]
    sgemm_nt<3><<<dim3(DM/128, TOK/128), blk>>>(nullptr, W_uv, nullptr, nullptr, TOK, DM, DL);
    // attention -> ctx              [4096, 2048] (already in [b,s,h*hd] order)
    attn_kernel<<<dim3(SEQ/32, NB*NH), dim3(128)>>>();
    // out = ctx @ W_o^T + b         [4096, 2048]
    sgemm_nt<4><<<dim3(DM/128, TOK/128), blk>>>(nullptr, W_o, W_b, out, TOK, DM, DM);
}

// round 3
// speedup vs baseline: 3.0653x; 3.0653x over previous
#include <cuda_runtime.h>

#define DM   2048     // d_model
#define DL   512      // d_latent
#define NH   16
#define HD   128
#define SEQ  2048
#define NB   2
#define TOK  (NB*SEQ) // 4096

// Scratch (allocation-free rule: __device__ globals, device-code refs only)
__device__ float g_q  [TOK*DM];
__device__ float g_ckv[TOK*DL];
__device__ float g_k  [TOK*DM];
__device__ float g_v  [TOK*DM];
__device__ float g_ctx[TOK*DM];

// ---------------------------------------------------------------------------
// C[M,N] = A[M,K] @ B[N,K]^T  (+ optional bias[N])   (unchanged from R2 pass)
// ---------------------------------------------------------------------------
template<int MODE>
__global__ __launch_bounds__(256) void sgemm_nt(
    const float* __restrict__ Aarg, const float* __restrict__ B,
    const float* __restrict__ bias, float* __restrict__ Carg,
    int M, int N, int K)
{
    const float* A;
    float* C;
    if      (MODE == 0) { A = Aarg;  C = g_ckv; }
    else if (MODE == 1) { A = Aarg;  C = g_q;   }
    else if (MODE == 2) { A = g_ckv; C = g_k;   }
    else if (MODE == 3) { A = g_ckv; C = g_v;   }
    else                { A = g_ctx; C = Carg;  }

    const int BK = 16;
    __shared__ float As[BK][128];
    __shared__ float Bs[BK][128];

    int tid  = threadIdx.x;
    int tx   = tid & 15;
    int ty   = tid >> 4;
    int row0 = blockIdx.y * 128;
    int col0 = blockIdx.x * 128;

    float acc[8][8];
#pragma unroll
    for (int i = 0; i < 8; i++)
#pragma unroll
        for (int j = 0; j < 8; j++) acc[i][j] = 0.f;

    int lr = tid >> 2;
    int lc = tid & 3;

    for (int k0 = 0; k0 < K; k0 += BK) {
#pragma unroll
        for (int l = 0; l < 2; l++) {
            int r = lr + l * 64;
            float4 va = *(const float4*)(A + (size_t)(row0 + r) * K + k0 + lc * 4);
            As[lc*4+0][r] = va.x; As[lc*4+1][r] = va.y;
            As[lc*4+2][r] = va.z; As[lc*4+3][r] = va.w;
            float4 vb = *(const float4*)(B + (size_t)(col0 + r) * K + k0 + lc * 4);
            Bs[lc*4+0][r] = vb.x; Bs[lc*4+1][r] = vb.y;
            Bs[lc*4+2][r] = vb.z; Bs[lc*4+3][r] = vb.w;
        }
        __syncthreads();

#pragma unroll
        for (int kk = 0; kk < BK; kk++) {
            float a[8], b[8];
#pragma unroll
            for (int i = 0; i < 8; i++) a[i] = As[kk][ty * 8 + i];
#pragma unroll
            for (int j = 0; j < 8; j++) b[j] = Bs[kk][tx * 8 + j];
#pragma unroll
            for (int i = 0; i < 8; i++)
#pragma unroll
                for (int j = 0; j < 8; j++)
                    acc[i][j] += a[i] * b[j];
        }
        __syncthreads();
    }

#pragma unroll
    for (int i = 0; i < 8; i++) {
        int row = row0 + ty * 8 + i;
#pragma unroll
        for (int j = 0; j < 8; j++) {
            int col = col0 + tx * 8 + j;
            float v = acc[i][j];
            if (MODE == 4) v += bias[col];
            C[(size_t)row * N + col] = v;
        }
    }
}

// ---------------------------------------------------------------------------
// Register-tiled causal flash attention, fp32.
// BQ=128 queries/block, BK=64 keys/tile, 256 threads, 1 CTA/SM.
// S phase: 8x4 tile/thread (Qt, Kt transposed in smem, float4 reads).
// PV phase: 8x8 tile/thread (Ps row-major, Vs natural).
// m/l/corr live in registers (row group of 16 threads computes identical
// values via xor-shuffle reductions).
// ---------------------------------------------------------------------------
#define ATTN_T   256
#define A_BQ     128
#define A_BK     64
#define QT_PITCH 132
#define KT_PITCH 68
#define PS_PITCH 68
#define SM_QT    0
#define SM_KT    (SM_QT + HD * QT_PITCH)          // 16896
#define SM_VS    (SM_KT + HD * KT_PITCH)          // 16896+8704=25600
#define SM_PS    (SM_VS + A_BK * HD)              // 25600+8192=33792
#define SM_FLOATS (SM_PS + A_BQ * PS_PITCH)       // 33792+8704=42496
#define ATTN_SMEM_BYTES (SM_FLOATS * 4)           // 169984

__global__ __launch_bounds__(ATTN_T, 1) void attn_kernel()
{
    extern __shared__ float sm[];
    float* Qt = sm + SM_QT;   // [HD][QT_PITCH]  Qt[d][r]
    float* Kt = sm + SM_KT;   // [HD][KT_PITCH]  Kt[d][c]
    float* Vs = sm + SM_VS;   // [A_BK][HD]      Vs[c][d]
    float* Ps = sm + SM_PS;   // [A_BQ][PS_PITCH] Ps[r][c]

    const int tid  = threadIdx.x;
    const int lane = tid & 31;
    const int warp = tid >> 5;
    const int bx   = gridDim.x - 1 - blockIdx.x;   // big causal blocks first
    const int bh   = blockIdx.y;
    const int b    = bh >> 4;
    const int h    = bh & 15;
    const int q0   = bx * A_BQ;

    const int ty = tid >> 4;       // 0..15 -> rows r0..r0+7
    const int tx = tid & 15;       // 0..15
    const int r0 = ty * 8;
    const int c0 = tx * 4;         // S cols
    const int d0 = tx * 8;         // O dims

    const int rsub = lane >> 2;            // 0..7 (transpose-load row)
    const int dg   = (warp << 2) + (lane & 3);  // 0..31 (float4 group)

    const float scale = 0.08838834764831845f;  // 1/sqrt(128)

    // ---- load Q transposed & scaled (once per block) ----
#pragma unroll
    for (int it = 0; it < 16; it++) {
        int r = it * 8 + rsub;  // 0..127
        float4 v = *(const float4*)(g_q + (size_t)(b*SEQ + q0 + r) * DM + h*HD + dg*4);
        Qt[(dg*4+0)*QT_PITCH + r] = v.x * scale;
        Qt[(dg*4+1)*QT_PITCH + r] = v.y * scale;
        Qt[(dg*4+2)*QT_PITCH + r] = v.z * scale;
        Qt[(dg*4+3)*QT_PITCH + r] = v.w * scale;
    }

    float o[8][8];
#pragma unroll
    for (int i = 0; i < 8; i++)
#pragma unroll
        for (int j = 0; j < 8; j++) o[i][j] = 0.f;
    float m[8], l[8];
#pragma unroll
    for (int i = 0; i < 8; i++) { m[i] = -1e30f; l[i] = 0.f; }

    const int nkt = (q0 + A_BQ) / A_BK;   // 2*bx+2
    for (int kt = 0; kt < nkt; kt++) {
        const int k0 = kt * A_BK;
        __syncthreads();   // prior PV done with Kt/Vs/Ps

        // load K transposed
#pragma unroll
        for (int it = 0; it < 8; it++) {
            int r = it * 8 + rsub;  // key 0..63
            float4 v = *(const float4*)(g_k + (size_t)(b*SEQ + k0 + r) * DM + h*HD + dg*4);
            Kt[(dg*4+0)*KT_PITCH + r] = v.x;
            Kt[(dg*4+1)*KT_PITCH + r] = v.y;
            Kt[(dg*4+2)*KT_PITCH + r] = v.z;
            Kt[(dg*4+3)*KT_PITCH + r] = v.w;
        }
        // load V natural
#pragma unroll
        for (int it = 0; it < 8; it++) {
            int idx = it * 256 + tid;
            int r  = idx >> 5;          // 0..63
            int dc = (idx & 31) * 4;
            float4 v = *(const float4*)(g_v + (size_t)(b*SEQ + k0 + r) * DM + h*HD + dc);
            *(float4*)(Vs + r * HD + dc) = v;
        }
        __syncthreads();

        // ---- S = Q @ K^T  (8x4 per thread) ----
        float s[8][4];
#pragma unroll
        for (int i = 0; i < 8; i++)
#pragma unroll
            for (int j = 0; j < 4; j++) s[i][j] = 0.f;

#pragma unroll 4
        for (int kk = 0; kk < HD; kk++) {
            float4 qa = *(const float4*)(Qt + kk*QT_PITCH + r0);
            float4 qb = *(const float4*)(Qt + kk*QT_PITCH + r0 + 4);
            float4 kv = *(const float4*)(Kt + kk*KT_PITCH + c0);
            float qr[8] = {qa.x,qa.y,qa.z,qa.w,qb.x,qb.y,qb.z,qb.w};
            float kr[4] = {kv.x,kv.y,kv.z,kv.w};
#pragma unroll
            for (int i = 0; i < 8; i++)
#pragma unroll
                for (int j = 0; j < 4; j++)
                    s[i][j] += qr[i] * kr[j];
        }

        // causal mask (only the two diagonal tiles need it)
        if (k0 + A_BK - 1 > q0) {
#pragma unroll
            for (int i = 0; i < 8; i++)
#pragma unroll
                for (int j = 0; j < 4; j++)
                    if (k0 + c0 + j > q0 + r0 + i) s[i][j] = -1e30f;
        }

        // ---- online softmax (row group = 16 lanes sharing ty) ----
        float cs[8];
#pragma unroll
        for (int i = 0; i < 8; i++) {
            float mx = fmaxf(fmaxf(s[i][0], s[i][1]), fmaxf(s[i][2], s[i][3]));
            mx = fmaxf(mx, __shfl_xor_sync(0xffffffffu, mx, 1));
            mx = fmaxf(mx, __shfl_xor_sync(0xffffffffu, mx, 2));
            mx = fmaxf(mx, __shfl_xor_sync(0xffffffffu, mx, 4));
            mx = fmaxf(mx, __shfl_xor_sync(0xffffffffu, mx, 8));
            float mn = fmaxf(m[i], mx);
            float p0 = __expf(s[i][0] - mn);
            float p1 = __expf(s[i][1] - mn);
            float p2 = __expf(s[i][2] - mn);
            float p3 = __expf(s[i][3] - mn);
            *(float4*)(Ps + (r0 + i) * PS_PITCH + c0) = make_float4(p0, p1, p2, p3);
            float sum = (p0 + p1) + (p2 + p3);
            sum += __shfl_xor_sync(0xffffffffu, sum, 1);
            sum += __shfl_xor_sync(0xffffffffu, sum, 2);
            sum += __shfl_xor_sync(0xffffffffu, sum, 4);
            sum += __shfl_xor_sync(0xffffffffu, sum, 8);
            float corr = __expf(m[i] - mn);
            l[i] = l[i] * corr + sum;
            m[i] = mn;
            cs[i] = corr;
        }
        __syncthreads();   // Ps visible to all

        // ---- O = O*corr + P @ V  (8x8 per thread) ----
#pragma unroll
        for (int i = 0; i < 8; i++)
#pragma unroll
            for (int j = 0; j < 8; j++) o[i][j] *= cs[i];

#pragma unroll 2
        for (int k4 = 0; k4 < A_BK; k4 += 4) {
            float4 p4[8];
#pragma unroll
            for (int i = 0; i < 8; i++)
                p4[i] = *(const float4*)(Ps + (r0 + i) * PS_PITCH + k4);
#pragma unroll
            for (int u = 0; u < 4; u++) {
                float4 va = *(const float4*)(Vs + (k4 + u) * HD + d0);
                float4 vb = *(const float4*)(Vs + (k4 + u) * HD + d0 + 4);
                float vv[8] = {va.x,va.y,va.z,va.w,vb.x,vb.y,vb.z,vb.w};
#pragma unroll
                for (int i = 0; i < 8; i++) {
                    float pu = (u == 0) ? p4[i].x : (u == 1) ? p4[i].y
                             : (u == 2) ? p4[i].z : p4[i].w;
#pragma unroll
                    for (int j = 0; j < 8; j++)
                        o[i][j] += pu * vv[j];
                }
            }
        }
    }

    // ---- normalize + store ----
#pragma unroll
    for (int i = 0; i < 8; i++) {
        float inv = 1.f / l[i];
        float* op = g_ctx + (size_t)(b*SEQ + q0 + r0 + i) * DM + h*HD + d0;
        float4 oa = make_float4(o[i][0]*inv, o[i][1]*inv, o[i][2]*inv, o[i][3]*inv);
        float4 ob = make_float4(o[i][4]*inv, o[i][5]*inv, o[i][6]*inv, o[i][7]*inv);
        *(float4*)(op)     = oa;
        *(float4*)(op + 4) = ob;
    }
}

// ---------------------------------------------------------------------------
// Launch: projections -> flash attention -> output projection (+bias)
// ---------------------------------------------------------------------------
extern "C" void kernel_launch(void* const* d_in, const int* in_sizes, int n_in,
                              void* d_out, int out_size)
{
    (void)in_sizes; (void)n_in; (void)out_size;
    const float* x    = (const float*)d_in[0];
    const float* W_q  = (const float*)d_in[1];
    const float* W_dkv= (const float*)d_in[2];
    const float* W_uk = (const float*)d_in[3];
    const float* W_uv = (const float*)d_in[4];
    const float* W_o  = (const float*)d_in[5];
    const float* W_b  = (const float*)d_in[6];
    float* out = (float*)d_out;

    cudaFuncSetAttribute(attn_kernel,
                         cudaFuncAttributeMaxDynamicSharedMemorySize,
                         ATTN_SMEM_BYTES);

    dim3 blk(256);
    sgemm_nt<0><<<dim3(DL/128, TOK/128), blk>>>(x, W_dkv, nullptr, nullptr, TOK, DL, DM);
    sgemm_nt<1><<<dim3(DM/128, TOK/128), blk>>>(x, W_q, nullptr, nullptr, TOK, DM, DM);
    sgemm_nt<2><<<dim3(DM/128, TOK/128), blk>>>(nullptr, W_uk, nullptr, nullptr, TOK, DM, DL);
    sgemm_nt<3><<<dim3(DM/128, TOK/128), blk>>>(nullptr, W_uv, nullptr, nullptr, TOK, DM, DL);
    attn_kernel<<<dim3(SEQ/A_BQ, NB*NH), dim3(ATTN_T), ATTN_SMEM_BYTES>>>();
    sgemm_nt<4><<<dim3(DM/128, TOK/128), blk>>>(nullptr, W_o, W_b, out, TOK, DM, DM);
}